// round 3
// baseline (speedup 1.0000x reference)
#include <cuda_runtime.h>

// Non-local means, 4 x 1 x 1024 x 1024 fp32.
// h = 7/255, template 7x7, search 21x21, reflect-101 padding everywhere.
//
// out(p) = sum_off w * shifted / sum_off w
//   w     = exp(-dist / h^2)
//   dist  = (1/49) * sum_{t in [-3,3]^2} D(refl(p+t))
//   D(q)  = (x(q) - x(refl(q + off)))^2 ,  off in [-10,10]^2
//
// Strategy: per-CTA SMEM tile storing x[refl(g)] indexed by unreflected global
// coordinate g (halo 13 = 10 search + 3 box). Vertical 7-box via register
// sliding window (ring of 7), horizontal 7-box via warp shuffles. Center
// column cached in 22 registers. Issue-bound design; HBM traffic negligible.

static constexpr int IMG_H = 1024;
static constexpr int IMG_W = 1024;
static constexpr int OUT_H = 32;     // CTA output rows
static constexpr int OUT_W = 104;    // CTA output cols = 4 warps * 26
static constexpr int REG_H = OUT_H + 26;   // 58
static constexpr int REG_W = OUT_W + 26;   // 130
static constexpr int NTHREADS = 256;

// dist/h^2 = boxsum/49 * (255/7)^2 = boxsum * 65025/2401
static constexpr float KCONST = 27.08246563931695f;

__device__ __forceinline__ int refl(int g, int n) {
    g = (g < 0) ? -g : g;
    return (g >= n) ? (2 * n - 2 - g) : g;
}

// Per-warp accumulation over all 441 offsets.
// RB: apply row reflection for the outer (box-filter) halo (edge row-strips only).
template <bool RB>
__device__ __forceinline__ void nlm_accum(
    const float* __restrict__ S,     // SMEM region
    const float* __restrict__ C,     // center column cache, 22 values
    float (&wacc)[16], float (&vacc)[16],
    int rw0,        // warp's first output row (global)
    int r0m13,      // r0 - 13 (SMEM row origin, global coords)
    int colB,       // SMEM col of this thread's (reflected) V-column
    int colS)       // SMEM col of this thread's output pixel (lane-clamped)
{
    #pragma unroll 1
    for (int dy = -10; dy <= 10; ++dy) {
        #pragma unroll 1
        for (int dx = -10; dx <= 10; ++dx) {
            const int cb = colB + dx;
            float d[7];
            float V = 0.0f;
            // warm-up: rows j = rw0-3 .. rw0+2
            #pragma unroll
            for (int m = 0; m < 6; ++m) {
                int j = rw0 - 3 + m;
                int qr = RB ? refl(j, IMG_H) : j;
                float bv = S[(qr + dy - r0m13) * REG_W + cb];
                float t = C[m] - bv;
                d[m] = t * t;
                V += d[m];
            }
            #pragma unroll
            for (int i = 0; i < 16; ++i) {
                int j = rw0 + 3 + i;
                int qr = RB ? refl(j, IMG_H) : j;
                float bv = S[(qr + dy - r0m13) * REG_W + cb];
                float t = C[i + 6] - bv;
                float dn = t * t;
                V += dn;                       // V = sum of E(i-3 .. i+3)
                d[(i + 6) % 7] = dn;
                // horizontal 7-sum across lanes: S7(l) = V(l) + ... + V(l+6)
                float p1 = V + __shfl_down_sync(0xffffffffu, V, 1);
                float p2 = p1 + __shfl_down_sync(0xffffffffu, p1, 2);
                float s7 = p2 + __shfl_down_sync(0xffffffffu, p1, 4)
                              + __shfl_down_sync(0xffffffffu, V, 6);
                float wgt = __expf(-KCONST * s7);
                float sh = S[(rw0 + i + dy - r0m13) * REG_W + colS + dx];
                wacc[i] += wgt;
                vacc[i] = fmaf(wgt, sh, vacc[i]);
                V -= d[i % 7];                 // drop E(i-3) for next row
            }
        }
    }
}

__global__ __launch_bounds__(NTHREADS, 3)
void nlm_kernel(const float* __restrict__ x, float* __restrict__ out) {
    __shared__ float S[REG_H * REG_W];

    const int b  = blockIdx.z;
    const int r0 = blockIdx.y * OUT_H;
    const int c0 = blockIdx.x * OUT_W;
    const int tid = threadIdx.x;

    // Load reflect-padded region: S[(g_r - (r0-13))*REG_W + (g_c - (c0-13))] = x[refl(g)]
    const float* xb = x + (size_t)b * (IMG_H * IMG_W);
    #pragma unroll 4
    for (int idx = tid; idx < REG_H * REG_W; idx += NTHREADS) {
        int i = idx / REG_W;
        int j = idx - i * REG_W;
        int gr = refl(r0 - 13 + i, IMG_H);
        int gc = refl(c0 - 13 + j, IMG_W);
        S[idx] = xb[gr * IMG_W + gc];
    }
    __syncthreads();

    const int w = tid >> 5, l = tid & 31;
    const int wx = w & 3, wy = w >> 2;
    const int rw0 = r0 + wy * 16;        // warp's first output row
    const int c0w = c0 + wx * 26;        // warp's first output col
    const int u = c0w - 3 + l;           // this lane's V column (unreflected)
    const int qc = refl(u, IMG_W);       // reflected column (fixed per thread)
    const int r0m13 = r0 - 13;
    const int c0m13 = c0 - 13;
    const int colB = qc - c0m13;
    const int lclamp = (l < 26) ? l : 25;
    const int colS = (c0w + lclamp) - c0m13;

    // Center column cache: C[m] = x(refl(rw0-3+m), qc)
    float C[22];
    #pragma unroll
    for (int m = 0; m < 22; ++m) {
        int qr = refl(rw0 - 3 + m, IMG_H);
        C[m] = S[(qr - r0m13) * REG_W + colB];
    }

    float wacc[16], vacc[16];
    #pragma unroll
    for (int i = 0; i < 16; ++i) { wacc[i] = 0.0f; vacc[i] = 0.0f; }

    const bool rowRefl = (rw0 - 3 < 0) || (rw0 + 18 >= IMG_H);
    if (!rowRefl) {
        nlm_accum<false>(S, C, wacc, vacc, rw0, r0m13, colB, colS);
    } else {
        nlm_accum<true>(S, C, wacc, vacc, rw0, r0m13, colB, colS);
    }

    // Write out: lanes 0..25 hold valid outputs
    const int cout = c0w + l;
    if (l < 26 && cout < IMG_W) {
        float* ob = out + (size_t)b * (IMG_H * IMG_W);
        #pragma unroll
        for (int i = 0; i < 16; ++i) {
            float q = vacc[i] / wacc[i];
            q = fminf(fmaxf(q, 0.0f), 1.0f);
            ob[(rw0 + i) * IMG_W + cout] = q;
        }
    }
}

extern "C" void kernel_launch(void* const* d_in, const int* in_sizes, int n_in,
                              void* d_out, int out_size) {
    const float* x = (const float*)d_in[0];
    float* out = (float*)d_out;
    (void)in_sizes; (void)n_in; (void)out_size;

    dim3 grid((IMG_W + OUT_W - 1) / OUT_W,   // 10
              IMG_H / OUT_H,                 // 32
              4);                            // batch
    dim3 block(NTHREADS);
    nlm_kernel<<<grid, block>>>(x, out);
}

// round 4
// speedup vs baseline: 1.5434x; 1.5434x over previous
#include <cuda_runtime.h>
#include <cuda_fp16.h>

// Non-local means, 4 x 1 x 1024 x 1024 fp32.
// h = 7/255, template 7x7, search 21x21, reflect-101 padding everywhere.
//
// Per-CTA SMEM tile stores x[refl(g)] indexed by unreflected global coords
// (halo 13 = 10 search + 3 box). Vertical 7-box: register sliding window.
// Horizontal 7-box: warp-shuffle tree on half2-packed PAIRS of rows
// (2 SHFL + 2 HADD2 per row instead of 4 SHFL + 4 FADD).
// exp scale folded into the diff so the weight is a single ex2.approx.

static constexpr int IMG_H = 1024;
static constexpr int IMG_W = 1024;
static constexpr int OUT_H = 32;     // CTA output rows
static constexpr int OUT_W = 104;    // CTA output cols = 4 warps * 26
static constexpr int REG_H = OUT_H + 26;   // 58
static constexpr int REG_W = OUT_W + 26;   // 130
static constexpr int NTHREADS = 256;

// dist/h^2 = boxsum/49 * (255/7)^2 = boxsum * 65025/2401 = K
// w = exp(-K*boxsum) = 2^(-K*log2e*boxsum);  C2 = K*log2e, SC = sqrt(C2)
static constexpr float SC = 6.2507390f;

__device__ __forceinline__ int refl(int g, int n) {
    g = (g < 0) ? -g : g;
    return (g >= n) ? (2 * n - 2 - g) : g;
}

__device__ __forceinline__ float ex2(float x) {
    float r;
    asm("ex2.approx.ftz.f32 %0, %1;" : "=f"(r) : "f"(x));
    return r;
}

// Per-warp accumulation over all 441 offsets.
// RB: apply row reflection for the outer (box) halo (edge row-strips only).
template <bool RB>
__device__ __forceinline__ void nlm_accum(
    const float* __restrict__ S,     // SMEM region
    const float* __restrict__ Cc,    // center column * SC, 22 values
    float (&wacc)[16], float (&vacc)[16],
    int rw0,        // warp's first output row (global)
    int r0m13,      // r0 - 13 (SMEM row origin, global coords)
    int colB,       // SMEM col of this thread's (reflected) V-column
    int colS)       // SMEM col of this thread's output pixel (lane-clamped)
{
    #pragma unroll 1
    for (int dy = -10; dy <= 10; ++dy) {
        #pragma unroll 1
        for (int dx = -10; dx <= 10; ++dx) {
            const int cb = colB + dx;
            const int cs = colS + dx;
            float d[7];
            float V = 0.0f;
            // warm-up: rows j = rw0-3 .. rw0+2
            #pragma unroll
            for (int m = 0; m < 6; ++m) {
                int j = rw0 - 3 + m;
                int qr = RB ? refl(j, IMG_H) : j;
                float bv = S[(qr + dy - r0m13) * REG_W + cb];
                float t = fmaf(-SC, bv, Cc[m]);
                d[m] = -t * t;
                V += d[m];
            }
            // main: rows processed in pairs, V = -C2 * (7-row vertical sum)
            #pragma unroll
            for (int i = 0; i < 16; i += 2) {
                {
                    int j = rw0 + 3 + i;
                    int qr = RB ? refl(j, IMG_H) : j;
                    float bv = S[(qr + dy - r0m13) * REG_W + cb];
                    float t = fmaf(-SC, bv, Cc[i + 6]);
                    float dn = -t * t;
                    V += dn;
                    d[(i + 6) % 7] = dn;
                }
                float Vlo = V;
                V -= d[i % 7];
                {
                    int j = rw0 + 4 + i;
                    int qr = RB ? refl(j, IMG_H) : j;
                    float bv = S[(qr + dy - r0m13) * REG_W + cb];
                    float t = fmaf(-SC, bv, Cc[i + 7]);
                    float dn = -t * t;
                    V += dn;
                    d[(i + 7) % 7] = dn;
                }
                float Vhi = V;
                V -= d[(i + 1) % 7];

                // horizontal 7-sum for two rows at once, packed in half2:
                // s7(l) = V(l)+...+V(l+6)
                __half2 h  = __floats2half2_rn(Vlo, Vhi);
                __half2 p1 = __hadd2(h,  __shfl_down_sync(0xffffffffu, h, 1));
                __half2 p2 = __hadd2(p1, __shfl_down_sync(0xffffffffu, p1, 2));
                __half2 s7 = __hadd2(p2,
                             __hadd2(__shfl_down_sync(0xffffffffu, p1, 4),
                                     __shfl_down_sync(0xffffffffu, h, 6)));
                float w0 = ex2(__low2float(s7));
                float w1 = ex2(__high2float(s7));
                float sh0 = S[(rw0 + i     + dy - r0m13) * REG_W + cs];
                float sh1 = S[(rw0 + i + 1 + dy - r0m13) * REG_W + cs];
                wacc[i]     += w0;
                vacc[i]      = fmaf(w0, sh0, vacc[i]);
                wacc[i + 1] += w1;
                vacc[i + 1]  = fmaf(w1, sh1, vacc[i + 1]);
            }
        }
    }
}

__global__ __launch_bounds__(NTHREADS, 2)
void nlm_kernel(const float* __restrict__ x, float* __restrict__ out) {
    __shared__ float S[REG_H * REG_W];

    const int b  = blockIdx.z;
    const int r0 = blockIdx.y * OUT_H;
    const int c0 = blockIdx.x * OUT_W;
    const int tid = threadIdx.x;

    // Load reflect-padded region: S[(gr-(r0-13))*REG_W + (gc-(c0-13))] = x[refl(g)]
    const float* xb = x + (size_t)b * (IMG_H * IMG_W);
    #pragma unroll 4
    for (int idx = tid; idx < REG_H * REG_W; idx += NTHREADS) {
        int i = idx / REG_W;
        int j = idx - i * REG_W;
        int gr = refl(r0 - 13 + i, IMG_H);
        int gc = refl(c0 - 13 + j, IMG_W);
        S[idx] = xb[gr * IMG_W + gc];
    }
    __syncthreads();

    const int w = tid >> 5, l = tid & 31;
    const int wx = w & 3, wy = w >> 2;
    const int rw0 = r0 + wy * 16;        // warp's first output row
    const int c0w = c0 + wx * 26;        // warp's first output col
    const int u = c0w - 3 + l;           // this lane's V column (unreflected)
    const int qc = refl(u, IMG_W);       // reflected column (fixed per thread)
    const int r0m13 = r0 - 13;
    const int c0m13 = c0 - 13;
    const int colB = qc - c0m13;
    const int lclamp = (l < 26) ? l : 25;
    const int colS = (c0w + lclamp) - c0m13;

    // Center column cache, pre-scaled: Cc[m] = SC * x(refl(rw0-3+m), qc)
    float Cc[22];
    #pragma unroll
    for (int m = 0; m < 22; ++m) {
        int qr = refl(rw0 - 3 + m, IMG_H);
        Cc[m] = SC * S[(qr - r0m13) * REG_W + colB];
    }

    float wacc[16], vacc[16];
    #pragma unroll
    for (int i = 0; i < 16; ++i) { wacc[i] = 0.0f; vacc[i] = 0.0f; }

    const bool rowRefl = (rw0 - 3 < 0) || (rw0 + 18 >= IMG_H);
    if (!rowRefl) {
        nlm_accum<false>(S, Cc, wacc, vacc, rw0, r0m13, colB, colS);
    } else {
        nlm_accum<true>(S, Cc, wacc, vacc, rw0, r0m13, colB, colS);
    }

    // Write out: lanes 0..25 hold valid outputs
    const int cout = c0w + l;
    if (l < 26 && cout < IMG_W) {
        float* ob = out + (size_t)b * (IMG_H * IMG_W);
        #pragma unroll
        for (int i = 0; i < 16; ++i) {
            float q = vacc[i] / wacc[i];
            q = fminf(fmaxf(q, 0.0f), 1.0f);
            ob[(rw0 + i) * IMG_W + cout] = q;
        }
    }
}

extern "C" void kernel_launch(void* const* d_in, const int* in_sizes, int n_in,
                              void* d_out, int out_size) {
    const float* x = (const float*)d_in[0];
    float* out = (float*)d_out;
    (void)in_sizes; (void)n_in; (void)out_size;

    dim3 grid((IMG_W + OUT_W - 1) / OUT_W,   // 10
              IMG_H / OUT_H,                 // 32
              4);                            // batch
    dim3 block(NTHREADS);
    nlm_kernel<<<grid, block>>>(x, out);
}